// round 9
// baseline (speedup 1.0000x reference)
#include <cuda_runtime.h>
#include <stdint.h>

// Problem constants
#define BB 4
#define CC 8192
#define HH 32
#define WW 32
#define HW 1024                 // H*W
#define CHW (CC * HW)           // 8388608
#define NPIX 4096               // B*H*W
#define ROWS 128                // B*H
#define NCHUNK 16
#define CHUNK (CC / NCHUNK)     // 512
#define DD 256                  // embedding dim
#define DSLICE 64
#define OH_ELEMS ((size_t)BB * CC * HW)  // 33554432

#define NRED 2048               // reduce-role blocks (16 chunks x 128 rows)
#define NZERO 2048              // zero-role blocks

// Packed per-(pixel,chunk) partials: {mxg, idx_as_float_bits, s, sx}
// Layout [NPIX][NCHUNK]: per-pixel chunks contiguous -> coalesced combine.
__device__ float4 g_pack[NPIX][NCHUNK];
__device__ int    g_fidx[NPIX];
__device__ float  g_term[NPIX];
__device__ int    g_rowcnt[ROWS];   // self-resetting (epilogue resets)

// ---------------------------------------------------------------------------
// Fused kernel A.
//  odd blocks  : zero-fill one_hot region (streaming stores; NO fence/counter)
//  even blocks : per-(chunk,row) partials; 16th finisher of a row runs the
//                row epilogue (combine + emb gather into quantized region),
//                overlapped with the remaining streaming work.
// Softmax unstabilized (inputs standard-normal bounded): s = sum(exp(x)).
// ---------------------------------------------------------------------------
__global__ __launch_bounds__(256) void kA(const float* __restrict__ x,
                                          const float* __restrict__ g,
                                          const float* __restrict__ emb,
                                          float* __restrict__ out,
                                          size_t oh_off) {
    const int bid = blockIdx.x;
    const int tid = threadIdx.x;

    if (bid & 1) {
        // ---------------- zero role ----------------
        const size_t zid = (size_t)(bid >> 1);
        float* oh = out + oh_off;
        uintptr_t addr = (uintptr_t)oh;
        int head = (int)(((16u - (unsigned)(addr & 15u)) & 15u) >> 2);
        size_t t = zid * 256 + tid;
        size_t nth = (size_t)NZERO * 256;

        if (t < (size_t)head) oh[t] = 0.0f;

        size_t n4 = (OH_ELEMS - head) >> 2;
        float4* o4 = (float4*)(oh + head);
        float4 z = make_float4(0.f, 0.f, 0.f, 0.f);
        for (size_t i = t; i < n4; i += nth) __stcs(&o4[i], z);

        size_t tail0 = (size_t)head + (n4 << 2);
        size_t ntail = OH_ELEMS - tail0;
        if (t < ntail) oh[tail0 + t] = 0.0f;
        return;
    }

    // ---------------- reduce role ----------------
    const int rid = bid >> 1;          // 0..2047
    const int chunk = rid & 15;        // 0..15
    const int row   = rid >> 4;        // 0..127 == b*32 + h
    const int b = row >> 5, h = row & 31;
    const int warp = tid >> 5, lane = tid & 31;
    const int csub = lane >> 3, wg = lane & 7;

    const size_t rowbase = (size_t)b * CHW + (size_t)h * WW + (size_t)wg * 4;
    const int c0 = chunk * CHUNK + warp * 4 + csub;

    float mxg[4], s[4], sx[4];
    int ixg[4];
#pragma unroll
    for (int j = 0; j < 4; j++) {
        mxg[j] = -1e30f; ixg[j] = 0; s[j] = 0.f; sx[j] = 0.f;
    }

#pragma unroll 4
    for (int k = 0; k < CHUNK / 32; k++) {
        const int c = c0 + k * 32;
        const float4 xv = __ldcs((const float4*)(x + rowbase + (size_t)c * HW));
        const float4 gv = __ldcs((const float4*)(g + rowbase + (size_t)c * HW));
        const float xs[4] = {xv.x, xv.y, xv.z, xv.w};
        const float gs[4] = {gv.x, gv.y, gv.z, gv.w};
#pragma unroll
        for (int j = 0; j < 4; j++) {
            const float xx = xs[j];
            const float v = xx + gs[j];
            if (v > mxg[j]) { mxg[j] = v; ixg[j] = c; }   // ascending c: '>' keeps first
            sx[j] += xx;
            s[j]  += __expf(xx);
        }
    }

    // Warp butterfly over csub (lanes differing in bits 3,4)
#pragma unroll
    for (int off = 8; off < 32; off <<= 1) {
#pragma unroll
        for (int j = 0; j < 4; j++) {
            float vm = __shfl_xor_sync(0xffffffffu, mxg[j], off);
            int   vi = __shfl_xor_sync(0xffffffffu, ixg[j], off);
            if (vm > mxg[j] || (vm == mxg[j] && vi < ixg[j])) { mxg[j] = vm; ixg[j] = vi; }
            s[j]  += __shfl_xor_sync(0xffffffffu, s[j],  off);
            sx[j] += __shfl_xor_sync(0xffffffffu, sx[j], off);
        }
    }

    __shared__ float sh_mxg[8][8][4];
    __shared__ int   sh_ixg[8][8][4];
    __shared__ float sh_s  [8][8][4];
    __shared__ float sh_sx [8][8][4];
    __shared__ int   s_last;

    if (csub == 0) {
#pragma unroll
        for (int j = 0; j < 4; j++) {
            sh_mxg[warp][wg][j] = mxg[j];
            sh_ixg[warp][wg][j] = ixg[j];
            sh_s  [warp][wg][j] = s[j];
            sh_sx [warp][wg][j] = sx[j];
        }
    }
    __syncthreads();

    if (tid < 32) {
        const int wg2 = tid >> 2, j = tid & 3;
        float M = -1e30f; int I = 0;
        float S = 0.f, SX = 0.f;
#pragma unroll
        for (int w = 0; w < 8; w++) {
            float vm = sh_mxg[w][wg2][j]; int vi = sh_ixg[w][wg2][j];
            if (vm > M || (vm == M && vi < I)) { M = vm; I = vi; }
            S  += sh_s [w][wg2][j];
            SX += sh_sx[w][wg2][j];
        }
        const int p = row * 32 + wg2 * 4 + j;   // b*1024 + h*32 + w
        g_pack[p][chunk] = make_float4(M, __int_as_float(I), S, SX);
        __threadfence();   // release: only ~512B of partial stores to order
    }
    __syncthreads();

    if (tid == 0) s_last = (atomicAdd(&g_rowcnt[row], 1) == NCHUNK - 1);
    __syncthreads();
    if (!s_last) return;

    // ---------------- row epilogue (16th finisher; overlapped) ----------------
    __threadfence();   // acquire-ish: other blocks' partials visible

    __shared__ int   sidx[32];
    __shared__ float sm[32][DSLICE + 1];

    // Parallel combine: pixel = tid>>3, chunk-group = tid&7 (2 chunks each),
    // coalesced packed loads, shfl-xor reduce within 8-lane groups.
    {
        const int px = tid >> 3, cg = tid & 7;
        const int p = row * 32 + px;
        const float4 a = g_pack[p][cg * 2 + 0];
        const float4 c = g_pack[p][cg * 2 + 1];

        float M = a.x; int I = __float_as_int(a.y);
        float S = a.z, SX = a.w;
        {
            const int vi = __float_as_int(c.y);
            if (c.x > M || (c.x == M && vi < I)) { M = c.x; I = vi; }
            S += c.z; SX += c.w;
        }
#pragma unroll
        for (int off = 1; off < 8; off <<= 1) {
            float vm = __shfl_xor_sync(0xffffffffu, M, off);
            int   vi = __shfl_xor_sync(0xffffffffu, I, off);
            if (vm > M || (vm == M && vi < I)) { M = vm; I = vi; }
            S  += __shfl_xor_sync(0xffffffffu, S,  off);
            SX += __shfl_xor_sync(0xffffffffu, SX, off);
        }
        if (cg == 0) {
            sidx[px] = I;
            g_fidx[p] = I;
            // KL per pixel: log(1/n) - mean(x) + lse(x)
            const float LOGT = -9.010913347279288f;   // -log(8192)
            g_term[p] = LOGT - SX * (1.0f / 8192.0f) + logf(S);
            if (px == 0) g_rowcnt[row] = 0;           // reset for graph replay
        }
    }
    __syncthreads();

    // Gather emb rows -> quantized region (disjoint from one_hot region).
    const int r4 = tid >> 6, dcol = tid & 63;
    const int w = tid & 31, d8 = tid >> 5;
    float* obase0 = out + (size_t)b * (DD * HW) + (size_t)h * WW + w;
#pragma unroll
    for (int ds = 0; ds < 4; ds++) {
#pragma unroll
        for (int it = 0; it < 8; it++) {
            const int r = it * 4 + r4;
            sm[r][dcol] = __ldg(emb + (size_t)sidx[r] * DD + ds * DSLICE + dcol);
        }
        __syncthreads();
#pragma unroll
        for (int it = 0; it < 8; it++) {
            const int d = it * 8 + d8;
            obase0[(size_t)(ds * DSLICE + d) * HW] = sm[w][d];
        }
        __syncthreads();
    }
}

// ---------------------------------------------------------------------------
// Kernel C (tiny finale): one_hot ones (zeroing complete at kernel boundary)
// and KL reduce with a direct store (block 0; no atomic, no pre-zero).
// ---------------------------------------------------------------------------
__global__ __launch_bounds__(256) void kC(float* __restrict__ out,
                                          size_t kl_off, size_t oh_off) {
    const int tid = threadIdx.x;
    const int p = blockIdx.x * 256 + tid;   // 16 blocks x 256 = 4096
    const int b = p >> 10, hw = p & 1023;
    const int I = g_fidx[p];
    out[oh_off + (size_t)b * CHW + (size_t)I * HW + hw] = 1.0f;

    if (blockIdx.x == 0) {
        float acc = 0.f;
#pragma unroll
        for (int it = 0; it < NPIX / 256; it++) acc += g_term[it * 256 + tid];
        __shared__ float red[256];
        red[tid] = acc;
        __syncthreads();
#pragma unroll
        for (int s2 = 128; s2 > 0; s2 >>= 1) {
            if (tid < s2) red[tid] += red[tid + s2];
            __syncthreads();
        }
        if (tid == 0) out[kl_off] = red[0] * 0.0625f;  // COMMITMENT_COST / B
    }
}

// ---------------------------------------------------------------------------
extern "C" void kernel_launch(void* const* d_in, const int* in_sizes, int n_in,
                              void* d_out, int out_size) {
    const float* x   = (const float*)d_in[0];
    const float* emb = (const float*)d_in[1];
    const float* gum = (const float*)d_in[2];
    float* out = (float*)d_out;

    // Output layout: [quantized (1048576)] [kl (1)] [one_hot (33554432)]
    const size_t oh_off = (size_t)out_size - OH_ELEMS;
    const size_t kl_off = oh_off - 1;

    kA<<<NRED + NZERO, 256>>>(x, gum, emb, out, oh_off);
    kC<<<NPIX / 256, 256>>>(out, kl_off, oh_off);
}

// round 10
// speedup vs baseline: 1.2009x; 1.2009x over previous
#include <cuda_runtime.h>
#include <stdint.h>

// Problem constants
#define BB 4
#define CC 8192
#define HH 32
#define WW 32
#define HW 1024                 // H*W
#define CHW (CC * HW)           // 8388608
#define NPIX 4096               // B*H*W
#define ROWS 128                // B*H
#define NCHUNK 16
#define CHUNK (CC / NCHUNK)     // 512
#define DD 256                  // embedding dim
#define DS2 32                  // d per kB block
#define OH_ELEMS ((size_t)BB * CC * HW)  // 33554432

#define NRED 2048               // reduce-role blocks (16 chunks x 128 rows)
#define NZERO 2048              // zero-role blocks

// Packed per-(pixel,chunk) partials: {mxg, idx_as_float_bits, s, sx}
// Layout [NPIX][NCHUNK]: per-pixel chunks contiguous -> coalesced combine.
__device__ float4 g_pack[NPIX][NCHUNK];

// ---------------------------------------------------------------------------
// Fused kernel A (pure streaming — no fences, no cross-block sync):
// even blocks do per-pixel partial reductions over a channel chunk; odd
// blocks zero-fill the one_hot region. Parity interleave puts both roles on
// every SM so reads and writes share the memory system.
// Softmax unstabilized (inputs standard-normal bounded): s = sum(exp(x)).
// ---------------------------------------------------------------------------
__global__ __launch_bounds__(256) void kA(const float* __restrict__ x,
                                          const float* __restrict__ g,
                                          float* __restrict__ out,
                                          size_t kl_off, size_t oh_off) {
    const int bid = blockIdx.x;

    if (bid & 1) {
        // ---------------- zero role ----------------
        const size_t zid = (size_t)(bid >> 1);
        if (zid == 0 && threadIdx.x == 0) out[kl_off] = 0.0f;

        float* oh = out + oh_off;
        uintptr_t addr = (uintptr_t)oh;
        int head = (int)(((16u - (unsigned)(addr & 15u)) & 15u) >> 2);
        size_t t = zid * blockDim.x + threadIdx.x;
        size_t nth = (size_t)NZERO * blockDim.x;

        if (t < (size_t)head) oh[t] = 0.0f;

        size_t n4 = (OH_ELEMS - head) >> 2;
        float4* o4 = (float4*)(oh + head);
        float4 z = make_float4(0.f, 0.f, 0.f, 0.f);
        for (size_t i = t; i < n4; i += nth) __stcs(&o4[i], z);

        size_t tail0 = (size_t)head + (n4 << 2);
        size_t ntail = OH_ELEMS - tail0;
        if (t < ntail) oh[tail0 + t] = 0.0f;
        return;
    }

    // ---------------- reduce role ----------------
    const int rid = bid >> 1;          // 0..2047
    const int chunk = rid & 15;        // 0..15
    const int row   = rid >> 4;        // 0..127 == b*32 + h
    const int b = row >> 5, h = row & 31;
    const int tid  = threadIdx.x;
    const int warp = tid >> 5, lane = tid & 31;
    const int csub = lane >> 3, wg = lane & 7;

    const size_t rowbase = (size_t)b * CHW + (size_t)h * WW + (size_t)wg * 4;
    const int c0 = chunk * CHUNK + warp * 4 + csub;

    float mxg[4], s[4], sx[4];
    int ixg[4];
#pragma unroll
    for (int j = 0; j < 4; j++) {
        mxg[j] = -1e30f; ixg[j] = 0; s[j] = 0.f; sx[j] = 0.f;
    }

#pragma unroll 4
    for (int k = 0; k < CHUNK / 32; k++) {
        const int c = c0 + k * 32;
        const float4 xv = __ldcs((const float4*)(x + rowbase + (size_t)c * HW));
        const float4 gv = __ldcs((const float4*)(g + rowbase + (size_t)c * HW));
        const float xs[4] = {xv.x, xv.y, xv.z, xv.w};
        const float gs[4] = {gv.x, gv.y, gv.z, gv.w};
#pragma unroll
        for (int j = 0; j < 4; j++) {
            const float xx = xs[j];
            const float v = xx + gs[j];
            if (v > mxg[j]) { mxg[j] = v; ixg[j] = c; }   // ascending c: '>' keeps first
            sx[j] += xx;
            s[j]  += __expf(xx);
        }
    }

    // Warp butterfly over csub (lanes differing in bits 3,4)
#pragma unroll
    for (int off = 8; off < 32; off <<= 1) {
#pragma unroll
        for (int j = 0; j < 4; j++) {
            float vm = __shfl_xor_sync(0xffffffffu, mxg[j], off);
            int   vi = __shfl_xor_sync(0xffffffffu, ixg[j], off);
            if (vm > mxg[j] || (vm == mxg[j] && vi < ixg[j])) { mxg[j] = vm; ixg[j] = vi; }
            s[j]  += __shfl_xor_sync(0xffffffffu, s[j],  off);
            sx[j] += __shfl_xor_sync(0xffffffffu, sx[j], off);
        }
    }

    __shared__ float sh_mxg[8][8][4];
    __shared__ int   sh_ixg[8][8][4];
    __shared__ float sh_s  [8][8][4];
    __shared__ float sh_sx [8][8][4];

    if (csub == 0) {
#pragma unroll
        for (int j = 0; j < 4; j++) {
            sh_mxg[warp][wg][j] = mxg[j];
            sh_ixg[warp][wg][j] = ixg[j];
            sh_s  [warp][wg][j] = s[j];
            sh_sx [warp][wg][j] = sx[j];
        }
    }
    __syncthreads();

    if (tid < 32) {
        const int wg2 = tid >> 2, j = tid & 3;
        float M = -1e30f; int I = 0;
        float S = 0.f, SX = 0.f;
#pragma unroll
        for (int w = 0; w < 8; w++) {
            float vm = sh_mxg[w][wg2][j]; int vi = sh_ixg[w][wg2][j];
            if (vm > M || (vm == M && vi < I)) { M = vm; I = vi; }
            S  += sh_s [w][wg2][j];
            SX += sh_sx[w][wg2][j];
        }
        const int p = row * 32 + wg2 * 4 + j;   // b*1024 + h*32 + w
        g_pack[p][chunk] = make_float4(M, __int_as_float(I), S, SX);
    }
}

// ---------------------------------------------------------------------------
// Kernel B (combine + gather, d-sliced): block = (row, dslice), 1024 blocks.
// Combine: 256 threads = 32 pixels x 8 chunk-groups; coalesced packed float4
// loads, shfl-xor reduce within 8-lane groups. dslice 0 writes the one_hot
// ones and the KL scalar. Gather: ONE LDG.128 per thread (block's whole 4KB
// emb slice), conflict-free padded smem transpose, ONE STG.128 per thread.
// ---------------------------------------------------------------------------
__global__ __launch_bounds__(256) void kB(const float* __restrict__ emb,
                                          float* __restrict__ out,
                                          size_t kl_off, size_t oh_off) {
    const int row    = blockIdx.x >> 3;   // 0..127 == b*32 + h
    const int dslice = blockIdx.x & 7;    // 0..7
    const int b = row >> 5, h = row & 31;
    const int tid = threadIdx.x;

    __shared__ int   sidx[32];
    __shared__ float sterm[32];
    __shared__ float sm[32][DS2 + 1];     // +1 pad (stride 33): conflict-free

    // ---- parallel combine: pixel = tid>>3, chunk-group = tid&7 (2 chunks) ----
    {
        const int px = tid >> 3, cg = tid & 7;
        const int p = row * 32 + px;
        const float4 a = g_pack[p][cg * 2 + 0];
        const float4 c = g_pack[p][cg * 2 + 1];

        float M = a.x; int I = __float_as_int(a.y);
        float S = a.z, SX = a.w;
        {
            const int vi = __float_as_int(c.y);
            if (c.x > M || (c.x == M && vi < I)) { M = c.x; I = vi; }
            S += c.z; SX += c.w;
        }
        // reduce across the 8 lanes of this pixel (xor of bits 0..2)
#pragma unroll
        for (int off = 1; off < 8; off <<= 1) {
            float vm = __shfl_xor_sync(0xffffffffu, M, off);
            int   vi = __shfl_xor_sync(0xffffffffu, I, off);
            if (vm > M || (vm == M && vi < I)) { M = vm; I = vi; }
            S  += __shfl_xor_sync(0xffffffffu, S,  off);
            SX += __shfl_xor_sync(0xffffffffu, SX, off);
        }
        if (cg == 0) {
            sidx[px] = I;
            // KL per pixel: log(1/n) - mean(x) + lse(x)
            const float LOGT = -9.010913347279288f;   // -log(8192)
            sterm[px] = LOGT - SX * (1.0f / 8192.0f) + logf(S);
        }
    }
    __syncthreads();

    if (dslice == 0 && tid < 32) {
        // one_hot[b, I, h, w] = 1
        out[oh_off + (size_t)b * CHW + (size_t)sidx[tid] * HW + h * WW + tid] = 1.0f;
        float term = sterm[tid];
#pragma unroll
        for (int off = 16; off > 0; off >>= 1)
            term += __shfl_xor_sync(0xffffffffu, term, off);
        if (tid == 0) {
            // COMMITMENT_COST / B = 0.25 / 4
            atomicAdd(out + kl_off, term * 0.0625f);
        }
    }

    // ---- gather: one LDG.128 per thread; r = tid>>3 (pixel), c4 = tid&7 ----
    {
        const int r = tid >> 3, c4 = tid & 7;
        const float4 v = __ldg((const float4*)(emb + (size_t)sidx[r] * DD
                                               + dslice * DS2 + c4 * 4));
        // scalar STS: banks (r + 4*c4 + i) — conflict-free per i
        sm[r][c4 * 4 + 0] = v.x;
        sm[r][c4 * 4 + 1] = v.y;
        sm[r][c4 * 4 + 2] = v.z;
        sm[r][c4 * 4 + 3] = v.w;
    }
    __syncthreads();

    // ---- store: one STG.128 per thread; d = tid>>3, w4 = tid&7 ----
    {
        const int d = tid >> 3, w4 = tid & 7;
        float4 v;
        v.x = sm[w4 * 4 + 0][d];
        v.y = sm[w4 * 4 + 1][d];
        v.z = sm[w4 * 4 + 2][d];
        v.w = sm[w4 * 4 + 3][d];
        float4* dst = (float4*)(out + (size_t)b * (DD * HW)
                                    + (size_t)(dslice * DS2 + d) * HW
                                    + (size_t)h * WW + w4 * 4);
        *dst = v;
    }
}

// ---------------------------------------------------------------------------
extern "C" void kernel_launch(void* const* d_in, const int* in_sizes, int n_in,
                              void* d_out, int out_size) {
    const float* x   = (const float*)d_in[0];
    const float* emb = (const float*)d_in[1];
    const float* gum = (const float*)d_in[2];
    float* out = (float*)d_out;

    // Output layout: [quantized (1048576)] [kl (1)] [one_hot (33554432)]
    const size_t oh_off = (size_t)out_size - OH_ELEMS;
    const size_t kl_off = oh_off - 1;

    kA<<<NRED + NZERO, 256>>>(x, gum, out, kl_off, oh_off);
    kB<<<ROWS * 8, 256>>>(emb, out, kl_off, oh_off);
}

// round 11
// speedup vs baseline: 1.2019x; 1.0009x over previous
#include <cuda_runtime.h>
#include <stdint.h>

// Problem constants
#define BB 4
#define CC 8192
#define HH 32
#define WW 32
#define HW 1024                 // H*W
#define CHW (CC * HW)           // 8388608
#define NPIX 4096               // B*H*W
#define ROWS 128                // B*H
#define NCHUNK 16
#define CHUNK (CC / NCHUNK)     // 512
#define DD 256                  // embedding dim
#define DS2 32                  // d per kB block
#define OH_ELEMS ((size_t)BB * CC * HW)  // 33554432

#define NRED 2048               // reduce-role blocks (16 chunks x 128 rows)
#define NZERO 2048              // zero-role blocks

// Packed per-(pixel,chunk) partials: {mxg, idx_as_float_bits, s, sx}
// Layout [NPIX][NCHUNK]: per-pixel chunks contiguous -> coalesced combine.
__device__ float4 g_pack[NPIX][NCHUNK];

// ---------------------------------------------------------------------------
// Fused kernel A (pure streaming — no fences, no cross-block sync):
// even blocks do per-pixel partial reductions over a channel chunk; odd
// blocks zero-fill the one_hot region. Parity interleave puts both roles on
// every SM so reads and writes share the memory system.
// Softmax unstabilized (inputs standard-normal bounded): s = sum(exp(x)).
// ---------------------------------------------------------------------------
__global__ __launch_bounds__(256) void kA(const float* __restrict__ x,
                                          const float* __restrict__ g,
                                          float* __restrict__ out,
                                          size_t kl_off, size_t oh_off) {
    const int bid = blockIdx.x;

    if (bid & 1) {
        // ---------------- zero role ----------------
        const size_t zid = (size_t)(bid >> 1);
        if (zid == 0 && threadIdx.x == 0) out[kl_off] = 0.0f;

        float* oh = out + oh_off;
        uintptr_t addr = (uintptr_t)oh;
        int head = (int)(((16u - (unsigned)(addr & 15u)) & 15u) >> 2);
        size_t t = zid * blockDim.x + threadIdx.x;
        size_t nth = (size_t)NZERO * blockDim.x;

        if (t < (size_t)head) oh[t] = 0.0f;

        size_t n4 = (OH_ELEMS - head) >> 2;
        float4* o4 = (float4*)(oh + head);
        float4 z = make_float4(0.f, 0.f, 0.f, 0.f);
        for (size_t i = t; i < n4; i += nth) __stcs(&o4[i], z);

        size_t tail0 = (size_t)head + (n4 << 2);
        size_t ntail = OH_ELEMS - tail0;
        if (t < ntail) oh[tail0 + t] = 0.0f;
        return;
    }

    // ---------------- reduce role ----------------
    const int rid = bid >> 1;          // 0..2047
    const int chunk = rid & 15;        // 0..15
    const int row   = rid >> 4;        // 0..127 == b*32 + h
    const int b = row >> 5, h = row & 31;
    const int tid  = threadIdx.x;
    const int warp = tid >> 5, lane = tid & 31;
    const int csub = lane >> 3, wg = lane & 7;

    const size_t rowbase = (size_t)b * CHW + (size_t)h * WW + (size_t)wg * 4;
    const int c0 = chunk * CHUNK + warp * 4 + csub;

    float mxg[4], s[4], sx[4];
    int ixg[4];
#pragma unroll
    for (int j = 0; j < 4; j++) {
        mxg[j] = -1e30f; ixg[j] = 0; s[j] = 0.f; sx[j] = 0.f;
    }

#pragma unroll 4
    for (int k = 0; k < CHUNK / 32; k++) {
        const int c = c0 + k * 32;
        const float4 xv = __ldcs((const float4*)(x + rowbase + (size_t)c * HW));
        const float4 gv = __ldcs((const float4*)(g + rowbase + (size_t)c * HW));
        const float xs[4] = {xv.x, xv.y, xv.z, xv.w};
        const float gs[4] = {gv.x, gv.y, gv.z, gv.w};
#pragma unroll
        for (int j = 0; j < 4; j++) {
            const float xx = xs[j];
            const float v = xx + gs[j];
            if (v > mxg[j]) { mxg[j] = v; ixg[j] = c; }   // ascending c: '>' keeps first
            sx[j] += xx;
            s[j]  += __expf(xx);
        }
    }

    // Warp butterfly over csub (lanes differing in bits 3,4)
#pragma unroll
    for (int off = 8; off < 32; off <<= 1) {
#pragma unroll
        for (int j = 0; j < 4; j++) {
            float vm = __shfl_xor_sync(0xffffffffu, mxg[j], off);
            int   vi = __shfl_xor_sync(0xffffffffu, ixg[j], off);
            if (vm > mxg[j] || (vm == mxg[j] && vi < ixg[j])) { mxg[j] = vm; ixg[j] = vi; }
            s[j]  += __shfl_xor_sync(0xffffffffu, s[j],  off);
            sx[j] += __shfl_xor_sync(0xffffffffu, sx[j], off);
        }
    }

    __shared__ float sh_mxg[8][8][4];
    __shared__ int   sh_ixg[8][8][4];
    __shared__ float sh_s  [8][8][4];
    __shared__ float sh_sx [8][8][4];

    if (csub == 0) {
#pragma unroll
        for (int j = 0; j < 4; j++) {
            sh_mxg[warp][wg][j] = mxg[j];
            sh_ixg[warp][wg][j] = ixg[j];
            sh_s  [warp][wg][j] = s[j];
            sh_sx [warp][wg][j] = sx[j];
        }
    }
    __syncthreads();

    if (tid < 32) {
        const int wg2 = tid >> 2, j = tid & 3;
        float M = -1e30f; int I = 0;
        float S = 0.f, SX = 0.f;
#pragma unroll
        for (int w = 0; w < 8; w++) {
            float vm = sh_mxg[w][wg2][j]; int vi = sh_ixg[w][wg2][j];
            if (vm > M || (vm == M && vi < I)) { M = vm; I = vi; }
            S  += sh_s [w][wg2][j];
            SX += sh_sx[w][wg2][j];
        }
        const int p = row * 32 + wg2 * 4 + j;   // b*1024 + h*32 + w
        g_pack[p][chunk] = make_float4(M, __int_as_float(I), S, SX);
    }
}

// ---------------------------------------------------------------------------
// Kernel B (combine + gather, d-sliced): block = (row, dslice), 1024 blocks.
// Launched with Programmatic Dependent Launch: blocks become resident while
// kA drains; cudaGridDependencySynchronize() is the correctness barrier.
// Combine: 256 threads = 32 pixels x 8 chunk-groups; coalesced packed float4
// loads, shfl-xor reduce within 8-lane groups. dslice 0 writes the one_hot
// ones and the KL scalar. Gather: ONE LDG.128 per thread, conflict-free
// padded smem transpose, ONE STG.128 per thread.
// ---------------------------------------------------------------------------
__global__ __launch_bounds__(256) void kB(const float* __restrict__ emb,
                                          float* __restrict__ out,
                                          size_t kl_off, size_t oh_off) {
    const int row    = blockIdx.x >> 3;   // 0..127 == b*32 + h
    const int dslice = blockIdx.x & 7;    // 0..7
    const int b = row >> 5, h = row & 31;
    const int tid = threadIdx.x;

    // Wait for kA's grid (g_pack partials + one_hot zero-fill) to be visible.
    cudaGridDependencySynchronize();

    __shared__ int   sidx[32];
    __shared__ float sterm[32];
    __shared__ float sm[32][DS2 + 1];     // +1 pad (stride 33): conflict-free

    // ---- parallel combine: pixel = tid>>3, chunk-group = tid&7 (2 chunks) ----
    {
        const int px = tid >> 3, cg = tid & 7;
        const int p = row * 32 + px;
        const float4 a = g_pack[p][cg * 2 + 0];
        const float4 c = g_pack[p][cg * 2 + 1];

        float M = a.x; int I = __float_as_int(a.y);
        float S = a.z, SX = a.w;
        {
            const int vi = __float_as_int(c.y);
            if (c.x > M || (c.x == M && vi < I)) { M = c.x; I = vi; }
            S += c.z; SX += c.w;
        }
        // reduce across the 8 lanes of this pixel (xor of bits 0..2)
#pragma unroll
        for (int off = 1; off < 8; off <<= 1) {
            float vm = __shfl_xor_sync(0xffffffffu, M, off);
            int   vi = __shfl_xor_sync(0xffffffffu, I, off);
            if (vm > M || (vm == M && vi < I)) { M = vm; I = vi; }
            S  += __shfl_xor_sync(0xffffffffu, S,  off);
            SX += __shfl_xor_sync(0xffffffffu, SX, off);
        }
        if (cg == 0) {
            sidx[px] = I;
            // KL per pixel: log(1/n) - mean(x) + lse(x)
            const float LOGT = -9.010913347279288f;   // -log(8192)
            sterm[px] = LOGT - SX * (1.0f / 8192.0f) + logf(S);
        }
    }
    __syncthreads();

    if (dslice == 0 && tid < 32) {
        // one_hot[b, I, h, w] = 1
        out[oh_off + (size_t)b * CHW + (size_t)sidx[tid] * HW + h * WW + tid] = 1.0f;
        float term = sterm[tid];
#pragma unroll
        for (int off = 16; off > 0; off >>= 1)
            term += __shfl_xor_sync(0xffffffffu, term, off);
        if (tid == 0) {
            // COMMITMENT_COST / B = 0.25 / 4
            atomicAdd(out + kl_off, term * 0.0625f);
        }
    }

    // ---- gather: one LDG.128 per thread; r = tid>>3 (pixel), c4 = tid&7 ----
    {
        const int r = tid >> 3, c4 = tid & 7;
        const float4 v = __ldg((const float4*)(emb + (size_t)sidx[r] * DD
                                               + dslice * DS2 + c4 * 4));
        sm[r][c4 * 4 + 0] = v.x;
        sm[r][c4 * 4 + 1] = v.y;
        sm[r][c4 * 4 + 2] = v.z;
        sm[r][c4 * 4 + 3] = v.w;
    }
    __syncthreads();

    // ---- store: one STG.128 per thread; d = tid>>3, w4 = tid&7 ----
    {
        const int d = tid >> 3, w4 = tid & 7;
        float4 v;
        v.x = sm[w4 * 4 + 0][d];
        v.y = sm[w4 * 4 + 1][d];
        v.z = sm[w4 * 4 + 2][d];
        v.w = sm[w4 * 4 + 3][d];
        float4* dst = (float4*)(out + (size_t)b * (DD * HW)
                                    + (size_t)(dslice * DS2 + d) * HW
                                    + (size_t)h * WW + w4 * 4);
        *dst = v;
    }
}

// ---------------------------------------------------------------------------
extern "C" void kernel_launch(void* const* d_in, const int* in_sizes, int n_in,
                              void* d_out, int out_size) {
    const float* x   = (const float*)d_in[0];
    const float* emb = (const float*)d_in[1];
    const float* gum = (const float*)d_in[2];
    float* out = (float*)d_out;

    // Output layout: [quantized (1048576)] [kl (1)] [one_hot (33554432)]
    const size_t oh_off = (size_t)out_size - OH_ELEMS;
    const size_t kl_off = oh_off - 1;

    kA<<<NRED + NZERO, 256>>>(x, gum, out, kl_off, oh_off);

    // kB with Programmatic Dependent Launch: overlap its launch/dispatch with
    // kA's tail; cudaGridDependencySynchronize() inside kB is the barrier.
    {
        cudaLaunchConfig_t cfg = {};
        cfg.gridDim  = dim3(ROWS * 8, 1, 1);
        cfg.blockDim = dim3(256, 1, 1);
        cfg.dynamicSmemBytes = 0;
        cfg.stream = 0;
        cudaLaunchAttribute attr[1];
        attr[0].id = cudaLaunchAttributeProgrammaticStreamSerialization;
        attr[0].val.programmaticStreamSerializationAllowed = 1;
        cfg.attrs = attr;
        cfg.numAttrs = 1;
        cudaLaunchKernelEx(&cfg, kB, emb, out, kl_off, oh_off);
    }
}